// round 2
// baseline (speedup 1.0000x reference)
#include <cuda_runtime.h>
#include <math.h>

#define BB 4
#define SS 2048
#define DM 1024
#define NH 16
#define HD 64
#define MT (BB*SS)          // 8192 rows
#define BSD (MT*DM)         // 8,388,608 elements per matrix

// Scratch (static device globals: allowed; no runtime allocation)
static __device__ float g_lin[3*BSD];    // qkv projections, later reused (slot 0) as attention output
static __device__ float g_heads[3*BSD];  // q,k,v in [b,h,s,d] layout (q,k RoPE'd)

// ---------------------------------------------------------------------------
// GEMM: C[m][n] = sum_k A[m][k] * W[n][k]   (x @ W^T), M=8192, N=K=1024
// 128x128 block tile, BK=16, 256 threads, 8x8 per-thread micro-tile.
// blockIdx.z selects among up to 3 weight matrices (QKV fused launch).
// ---------------------------------------------------------------------------
__global__ void __launch_bounds__(256) gemm_xwT(
    const float* __restrict__ A,
    const float* __restrict__ W0, const float* __restrict__ W1, const float* __restrict__ W2,
    float* __restrict__ C)
{
    const int K = DM, N = DM;
    const int z = blockIdx.z;
    const float* __restrict__ Wp = (z == 0) ? W0 : (z == 1 ? W1 : W2);
    float* Cp = C + (size_t)z * BSD;

    __shared__ float As[16][128];   // As[k][m]
    __shared__ float Bs[16][128];   // Bs[k][n]

    const int tid = threadIdx.x;
    const int tx = tid & 15, ty = tid >> 4;
    const int m0 = blockIdx.y * 128;
    const int n0 = blockIdx.x * 128;

    float acc[8][8];
    #pragma unroll
    for (int i = 0; i < 8; i++)
        #pragma unroll
        for (int j = 0; j < 8; j++) acc[i][j] = 0.0f;

    for (int kt = 0; kt < K; kt += 16) {
        #pragma unroll
        for (int r = 0; r < 2; r++) {
            int f   = tid * 2 + r;
            int row = f >> 2;           // 0..127
            int c4  = (f & 3) << 2;     // 0,4,8,12
            float4 va = *(const float4*)(A  + (size_t)(m0 + row) * K + kt + c4);
            As[c4+0][row] = va.x; As[c4+1][row] = va.y;
            As[c4+2][row] = va.z; As[c4+3][row] = va.w;
            float4 vb = *(const float4*)(Wp + (size_t)(n0 + row) * K + kt + c4);
            Bs[c4+0][row] = vb.x; Bs[c4+1][row] = vb.y;
            Bs[c4+2][row] = vb.z; Bs[c4+3][row] = vb.w;
        }
        __syncthreads();
        #pragma unroll
        for (int k = 0; k < 16; k++) {
            float a[8], b[8];
            *(float4*)&a[0] = *(const float4*)&As[k][ty*8];
            *(float4*)&a[4] = *(const float4*)&As[k][ty*8+4];
            *(float4*)&b[0] = *(const float4*)&Bs[k][tx*8];
            *(float4*)&b[4] = *(const float4*)&Bs[k][tx*8+4];
            #pragma unroll
            for (int i = 0; i < 8; i++)
                #pragma unroll
                for (int j = 0; j < 8; j++)
                    acc[i][j] = fmaf(a[i], b[j], acc[i][j]);
        }
        __syncthreads();
    }

    #pragma unroll
    for (int i = 0; i < 8; i++) {
        float* cp = Cp + (size_t)(m0 + ty*8 + i) * N + n0 + tx*8;
        *(float4*)(cp)     = make_float4(acc[i][0], acc[i][1], acc[i][2], acc[i][3]);
        *(float4*)(cp + 4) = make_float4(acc[i][4], acc[i][5], acc[i][6], acc[i][7]);
    }
}

// ---------------------------------------------------------------------------
// RoPE + head split: g_lin[mat][b*S+s][D] -> g_heads[mat][b*H+h][s][HD]
// RoPE on mat 0 (q), 1 (k); mat 2 (v) pass-through. One thread per even/odd pair.
// ---------------------------------------------------------------------------
__global__ void rope_split(const int* __restrict__ pos)
{
    const int total = 3 * BB * SS * NH * (HD/2);
    int i = blockIdx.x * blockDim.x + threadIdx.x;
    if (i >= total) return;

    int p = i & 31;  int t = i >> 5;     // pair index 0..31
    int h = t & (NH - 1);   t >>= 4;
    int s = t & (SS - 1);   t >>= 11;
    int b = t & (BB - 1);   int mat = t >> 2;

    const float* src = g_lin + (size_t)mat * BSD + (size_t)(b * SS + s) * DM + h * HD + 2 * p;
    float e = src[0], o = src[1];

    if (mat < 2) {
        int   ps  = pos[b * SS + s];
        // inv_freq = THETA^(-(2p)/HD), THETA=1e4 ; log(1e4)=9.210340372
        float ifr = __expf(-((float)(2 * p) * (1.0f / HD)) * 9.210340371976184f);
        float ang = (float)ps * ifr;
        float sn, cs;
        sincosf(ang, &sn, &cs);
        float e2 = e * cs - o * sn;
        o        = e * sn + o * cs;
        e = e2;
    }

    float* dst = g_heads + (size_t)mat * BSD + ((size_t)(b * NH + h) * SS + s) * HD + 2 * p;
    dst[0] = e; dst[1] = o;
}

// ---------------------------------------------------------------------------
// Streaming causal attention (flash style). Per block: one (b,h), 64 query rows.
// Tiles: Qs[d][m], Ks[d][n], Vs[n][d], Ps[m][n] in dynamic smem (68-float rows).
// 256 threads = 16x16 grid, 4x4 micro-tiles, online softmax via 16-lane shuffles.
// Output written into g_lin (reused) in [b][s][h*HD+d] layout for the WO GEMM.
// ---------------------------------------------------------------------------
#define SROW 68
#define ATTN_SMEM (4 * 64 * SROW * 4)

__global__ void __launch_bounds__(256) attn_fwd()
{
    extern __shared__ float sm[];
    float* Qs = sm;                  // [64][SROW]  Qs[d*SROW+m]
    float* Ks = sm + 64*SROW;        // [64][SROW]  Ks[d*SROW+n]
    float* Vs = sm + 2*64*SROW;      // [64][SROW]  Vs[n*SROW+d]
    float* Ps = sm + 3*64*SROW;      // [64][SROW]  Ps[m*SROW+n]

    const int tid = threadIdx.x;
    const int tx = tid & 15, ty = tid >> 4;
    const int qt = blockIdx.x;       // query tile 0..31
    const int bh = blockIdx.y;       // 0..63
    const int s0 = qt * 64;

    const float* Qg = g_heads +                 ((size_t)bh * SS + s0) * HD;
    const float* Kg = g_heads + (size_t)BSD   + (size_t)bh * SS * HD;
    const float* Vg = g_heads + 2*(size_t)BSD + (size_t)bh * SS * HD;

    // Load Q tile transposed: Qs[d][m]
    {
        int m = tid >> 2;
        #pragma unroll
        for (int r = 0; r < 4; r++) {
            int d = ((tid & 3) << 4) + r * 4;
            float4 v = *(const float4*)(Qg + (size_t)m * HD + d);
            Qs[(d+0)*SROW + m] = v.x; Qs[(d+1)*SROW + m] = v.y;
            Qs[(d+2)*SROW + m] = v.z; Qs[(d+3)*SROW + m] = v.w;
        }
    }

    float o_acc[4][4];
    float row_max[4], row_l[4];
    #pragma unroll
    for (int i = 0; i < 4; i++) {
        row_max[i] = -1e30f; row_l[i] = 0.0f;
        #pragma unroll
        for (int j = 0; j < 4; j++) o_acc[i][j] = 0.0f;
    }

    const float scale = 0.125f;  // 1/sqrt(64)

    for (int kb = 0; kb <= qt; kb++) {
        // Load K (transposed) and V (direct) tiles
        {
            const float* kg = Kg + (size_t)kb * 64 * HD;
            const float* vg = Vg + (size_t)kb * 64 * HD;
            int n = tid >> 2;
            #pragma unroll
            for (int r = 0; r < 4; r++) {
                int d = ((tid & 3) << 4) + r * 4;
                float4 kv = *(const float4*)(kg + (size_t)n * HD + d);
                Ks[(d+0)*SROW + n] = kv.x; Ks[(d+1)*SROW + n] = kv.y;
                Ks[(d+2)*SROW + n] = kv.z; Ks[(d+3)*SROW + n] = kv.w;
                float4 vv = *(const float4*)(vg + (size_t)n * HD + d);
                *(float4*)&Vs[n*SROW + d] = vv;
            }
        }
        __syncthreads();

        // GEMM1: S = Q K^T  (k-dim = head dim)
        float sacc[4][4];
        #pragma unroll
        for (int i = 0; i < 4; i++)
            #pragma unroll
            for (int j = 0; j < 4; j++) sacc[i][j] = 0.0f;

        #pragma unroll
        for (int d = 0; d < 64; d++) {
            float4 a = *(const float4*)&Qs[d*SROW + ty*4];
            float4 b = *(const float4*)&Ks[d*SROW + tx*4];
            float av[4] = {a.x, a.y, a.z, a.w};
            float bv[4] = {b.x, b.y, b.z, b.w};
            #pragma unroll
            for (int i = 0; i < 4; i++)
                #pragma unroll
                for (int j = 0; j < 4; j++)
                    sacc[i][j] = fmaf(av[i], bv[j], sacc[i][j]);
        }

        const bool diag = (kb == qt);
        float corr[4];
        #pragma unroll
        for (int i = 0; i < 4; i++) {
            float mx = -1e30f;
            #pragma unroll
            for (int j = 0; j < 4; j++) {
                float sv = sacc[i][j] * scale;
                if (diag) {
                    int gi = ty*4 + i;         // local row == global offset within tile
                    int gj = tx*4 + j;
                    if (gj > gi) sv = -1e30f;
                }
                sacc[i][j] = sv;
                mx = fmaxf(mx, sv);
            }
            #pragma unroll
            for (int off = 8; off >= 1; off >>= 1)
                mx = fmaxf(mx, __shfl_xor_sync(0xffffffffu, mx, off));
            float mnew = fmaxf(row_max[i], mx);
            corr[i] = __expf(row_max[i] - mnew);
            row_max[i] = mnew;
            float ps = 0.0f;
            #pragma unroll
            for (int j = 0; j < 4; j++) {
                float p = __expf(sacc[i][j] - mnew);
                Ps[(ty*4 + i)*SROW + tx*4 + j] = p;
                ps += p;
            }
            #pragma unroll
            for (int off = 8; off >= 1; off >>= 1)
                ps += __shfl_xor_sync(0xffffffffu, ps, off);
            row_l[i] = row_l[i] * corr[i] + ps;
        }
        __syncthreads();

        // GEMM2: O += P V (rescale old accumulator first)
        #pragma unroll
        for (int i = 0; i < 4; i++)
            #pragma unroll
            for (int j = 0; j < 4; j++) o_acc[i][j] *= corr[i];

        #pragma unroll
        for (int n = 0; n < 64; n++) {
            float4 b = *(const float4*)&Vs[n*SROW + tx*4];
            float bv[4] = {b.x, b.y, b.z, b.w};
            float av[4];
            #pragma unroll
            for (int i = 0; i < 4; i++) av[i] = Ps[(ty*4 + i)*SROW + n];
            #pragma unroll
            for (int i = 0; i < 4; i++)
                #pragma unroll
                for (int j = 0; j < 4; j++)
                    o_acc[i][j] = fmaf(av[i], bv[j], o_acc[i][j]);
        }
        __syncthreads();
    }

    // Write normalized output: g_lin[(b*S + s)*D + h*HD + d]
    const int b = bh >> 4, h = bh & 15;
    #pragma unroll
    for (int i = 0; i < 4; i++) {
        float inv = 1.0f / row_l[i];
        float4 o = make_float4(o_acc[i][0]*inv, o_acc[i][1]*inv,
                               o_acc[i][2]*inv, o_acc[i][3]*inv);
        *(float4*)(g_lin + ((size_t)(b * SS + s0 + ty*4 + i)) * DM + h * HD + tx*4) = o;
    }
}

// ---------------------------------------------------------------------------
extern "C" void kernel_launch(void* const* d_in, const int* in_sizes, int n_in,
                              void* d_out, int out_size)
{
    const float* x  = (const float*)d_in[0];
    const int*  pos = (const int*)  d_in[1];
    const float* wq = (const float*)d_in[2];
    const float* wk = (const float*)d_in[3];
    const float* wv = (const float*)d_in[4];
    const float* wo = (const float*)d_in[5];
    float* out = (float*)d_out;

    void* lin_p = nullptr;
    cudaGetSymbolAddress(&lin_p, g_lin);
    float* lin = (float*)lin_p;

    cudaFuncSetAttribute(attn_fwd, cudaFuncAttributeMaxDynamicSharedMemorySize, ATTN_SMEM);

    // 1) q,k,v = x @ {wq,wk,wv}^T
    gemm_xwT<<<dim3(DM/128, MT/128, 3), 256>>>(x, wq, wk, wv, lin);

    // 2) RoPE + head split
    const int total = 3 * BB * SS * NH * (HD/2);
    rope_split<<<(total + 255) / 256, 256>>>(pos);

    // 3) causal attention (writes back into g_lin in [b,s,D] layout)
    attn_fwd<<<dim3(SS/64, BB*NH), 256, ATTN_SMEM>>>();

    // 4) out = attn @ wo^T
    gemm_xwT<<<dim3(DM/128, MT/128, 1), 256>>>(lin, wo, wo, wo, out);
}

// round 3
// speedup vs baseline: 1.0361x; 1.0361x over previous
#include <cuda_runtime.h>
#include <math.h>

#define BB 4
#define SS 2048
#define DM 1024
#define NH 16
#define HD 64
#define MT (BB*SS)          // 8192 rows
#define BSD (MT*DM)         // 8,388,608 elements per matrix

// Scratch (static device globals: allowed; no runtime allocation)
static __device__ float g_lin[3*BSD];    // qkv projections, later reused (slot 0) as attention output
static __device__ float g_heads[3*BSD];  // q,k,v in [b,h,s,d] layout (q,k RoPE'd)

// ---------------------------------------------------------------------------
// GEMM: C[m][n] = sum_k A[m][k] * W[n][k]   (x @ W^T), M=8192, N=K=1024
// 128x128 block tile, BK=16, 256 threads, 8x8 per-thread micro-tile.
// blockIdx.z selects among up to 3 weight matrices (QKV fused launch).
// ---------------------------------------------------------------------------
__global__ void __launch_bounds__(256) gemm_xwT(
    const float* __restrict__ A,
    const float* __restrict__ W0, const float* __restrict__ W1, const float* __restrict__ W2,
    float* __restrict__ C)
{
    const int K = DM, N = DM;
    const int z = blockIdx.z;
    const float* __restrict__ Wp = (z == 0) ? W0 : (z == 1 ? W1 : W2);
    float* Cp = C + (size_t)z * BSD;

    __shared__ float As[16][128];   // As[k][m]
    __shared__ float Bs[16][128];   // Bs[k][n]

    const int tid = threadIdx.x;
    const int tx = tid & 15, ty = tid >> 4;
    const int m0 = blockIdx.y * 128;
    const int n0 = blockIdx.x * 128;

    float acc[8][8];
    #pragma unroll
    for (int i = 0; i < 8; i++)
        #pragma unroll
        for (int j = 0; j < 8; j++) acc[i][j] = 0.0f;

    for (int kt = 0; kt < K; kt += 16) {
        #pragma unroll
        for (int r = 0; r < 2; r++) {
            int f   = tid * 2 + r;
            int row = f >> 2;           // 0..127
            int c4  = (f & 3) << 2;     // 0,4,8,12
            float4 va = *(const float4*)(A  + (size_t)(m0 + row) * K + kt + c4);
            As[c4+0][row] = va.x; As[c4+1][row] = va.y;
            As[c4+2][row] = va.z; As[c4+3][row] = va.w;
            float4 vb = *(const float4*)(Wp + (size_t)(n0 + row) * K + kt + c4);
            Bs[c4+0][row] = vb.x; Bs[c4+1][row] = vb.y;
            Bs[c4+2][row] = vb.z; Bs[c4+3][row] = vb.w;
        }
        __syncthreads();
        #pragma unroll
        for (int k = 0; k < 16; k++) {
            float a[8], b[8];
            *(float4*)&a[0] = *(const float4*)&As[k][ty*8];
            *(float4*)&a[4] = *(const float4*)&As[k][ty*8+4];
            *(float4*)&b[0] = *(const float4*)&Bs[k][tx*8];
            *(float4*)&b[4] = *(const float4*)&Bs[k][tx*8+4];
            #pragma unroll
            for (int i = 0; i < 8; i++)
                #pragma unroll
                for (int j = 0; j < 8; j++)
                    acc[i][j] = fmaf(a[i], b[j], acc[i][j]);
        }
        __syncthreads();
    }

    #pragma unroll
    for (int i = 0; i < 8; i++) {
        float* cp = Cp + (size_t)(m0 + ty*8 + i) * N + n0 + tx*8;
        *(float4*)(cp)     = make_float4(acc[i][0], acc[i][1], acc[i][2], acc[i][3]);
        *(float4*)(cp + 4) = make_float4(acc[i][4], acc[i][5], acc[i][6], acc[i][7]);
    }
}

// ---------------------------------------------------------------------------
// RoPE + head split: g_lin[mat][b*S+s][D] -> g_heads[mat][b*H+h][s][HD]
// RoPE on mat 0 (q), 1 (k); mat 2 (v) pass-through. One thread per even/odd pair.
// ---------------------------------------------------------------------------
__global__ void rope_split(const int* __restrict__ pos)
{
    const int total = 3 * BB * SS * NH * (HD/2);
    int i = blockIdx.x * blockDim.x + threadIdx.x;
    if (i >= total) return;

    int p = i & 31;  int t = i >> 5;     // pair index 0..31
    int h = t & (NH - 1);   t >>= 4;
    int s = t & (SS - 1);   t >>= 11;
    int b = t & (BB - 1);   int mat = t >> 2;

    const float* src = g_lin + (size_t)mat * BSD + (size_t)(b * SS + s) * DM + h * HD + 2 * p;
    float e = src[0], o = src[1];

    if (mat < 2) {
        int   ps  = pos[b * SS + s];
        float ifr = __expf(-((float)(2 * p) * (1.0f / HD)) * 9.210340371976184f);
        float ang = (float)ps * ifr;
        float sn, cs;
        sincosf(ang, &sn, &cs);
        float e2 = e * cs - o * sn;
        o        = e * sn + o * cs;
        e = e2;
    }

    float* dst = g_heads + (size_t)mat * BSD + ((size_t)(b * NH + h) * SS + s) * HD + 2 * p;
    dst[0] = e; dst[1] = o;
}

// ---------------------------------------------------------------------------
// Streaming causal attention, v2. Per block: one (b,h), 128 query rows, key
// tiles of 64. 256 threads = 16(ty rows) x 16(tx), 8x4 micro-tiles.
// Smem: Qs[d][m] (d-major), Ks[d][n] (d-major), Vs[n][d], Ps[m][n] row-major.
// All smem traffic is LDS.128/STS.128, broadcast- or conflict-free.
// ---------------------------------------------------------------------------
#define BM 128
#define BN 64
#define QROW 136
#define KROW 68
#define PROW 68
#define ATTN_SMEM ((64*QROW + 64*KROW + 64*KROW + BM*PROW) * 4)

__global__ void __launch_bounds__(256, 2) attn_fwd()
{
    extern __shared__ float sm[];
    float* Qs = sm;                       // [64][QROW]
    float* Ks = Qs + 64*QROW;             // [64][KROW]
    float* Vs = Ks + 64*KROW;             // [64][KROW]  Vs[n][d]
    float* Ps = Vs + 64*KROW;             // [BM][PROW]  Ps[m][n]

    const int tid = threadIdx.x;
    const int tx = tid & 15, ty = tid >> 4;
    const int qt = (int)gridDim.x - 1 - (int)blockIdx.x;  // long blocks first
    const int bh = blockIdx.y;
    const int s0 = qt * BM;

    const float* Qg = g_heads +                 ((size_t)bh * SS + s0) * HD;
    const float* Kg = g_heads + (size_t)BSD   + (size_t)bh * SS * HD;
    const float* Vg = g_heads + 2*(size_t)BSD + (size_t)bh * SS * HD;

    // Load Q tile transposed: Qs[d][m]. 128 rows x 64 cols, 2 threads/row.
    {
        int m  = tid >> 1;
        int c0 = (tid & 1) * 32;
        #pragma unroll
        for (int r = 0; r < 8; r++) {
            int d = c0 + r * 4;
            float4 v = *(const float4*)(Qg + (size_t)m * HD + d);
            Qs[(d+0)*QROW + m] = v.x; Qs[(d+1)*QROW + m] = v.y;
            Qs[(d+2)*QROW + m] = v.z; Qs[(d+3)*QROW + m] = v.w;
        }
    }

    float o_acc[8][4];
    float row_max[8], row_l[8];
    #pragma unroll
    for (int i = 0; i < 8; i++) {
        row_max[i] = -1e30f; row_l[i] = 0.0f;
        #pragma unroll
        for (int j = 0; j < 4; j++) o_acc[i][j] = 0.0f;
    }

    const float scale = 0.125f;  // 1/sqrt(64)
    const int nkt = 2 * qt + 2;

    for (int kb = 0; kb < nkt; kb++) {
        // Load K (transposed) and V tiles: 64 rows, 4 threads/row.
        {
            const float* kg = Kg + (size_t)kb * BN * HD;
            const float* vg = Vg + (size_t)kb * BN * HD;
            int n  = tid >> 2;
            int d0 = (tid & 3) * 16;
            #pragma unroll
            for (int r = 0; r < 4; r++) {
                int d = d0 + r * 4;
                float4 kv = *(const float4*)(kg + (size_t)n * HD + d);
                Ks[(d+0)*KROW + n] = kv.x; Ks[(d+1)*KROW + n] = kv.y;
                Ks[(d+2)*KROW + n] = kv.z; Ks[(d+3)*KROW + n] = kv.w;
                float4 vv = *(const float4*)(vg + (size_t)n * HD + d);
                *(float4*)&Vs[n*KROW + d] = vv;
            }
        }
        __syncthreads();

        // GEMM1: S = Q K^T
        float sacc[8][4];
        #pragma unroll
        for (int i = 0; i < 8; i++)
            #pragma unroll
            for (int j = 0; j < 4; j++) sacc[i][j] = 0.0f;

        #pragma unroll
        for (int d = 0; d < 64; d++) {
            float a[8];
            *(float4*)&a[0] = *(const float4*)&Qs[d*QROW + ty*8];
            *(float4*)&a[4] = *(const float4*)&Qs[d*QROW + ty*8 + 4];
            float4 bq = *(const float4*)&Ks[d*KROW + tx*4];
            float b[4] = {bq.x, bq.y, bq.z, bq.w};
            #pragma unroll
            for (int i = 0; i < 8; i++)
                #pragma unroll
                for (int j = 0; j < 4; j++)
                    sacc[i][j] = fmaf(a[i], b[j], sacc[i][j]);
        }

        // Online softmax; write P row-major (vectorized)
        const bool tilemask = (kb >= 2 * qt);
        const int noff = kb * BN - s0;     // (global n) - s0
        #pragma unroll
        for (int i = 0; i < 8; i++) {
            const int mrow = ty * 8 + i;
            float mx = -1e30f;
            #pragma unroll
            for (int j = 0; j < 4; j++) {
                float sv = sacc[i][j] * scale;
                if (tilemask && (noff + tx*4 + j > mrow)) sv = -1e30f;
                sacc[i][j] = sv;
                mx = fmaxf(mx, sv);
            }
            #pragma unroll
            for (int off = 8; off >= 1; off >>= 1)
                mx = fmaxf(mx, __shfl_xor_sync(0xffffffffu, mx, off));
            float mnew = fmaxf(row_max[i], mx);
            float corr = __expf(row_max[i] - mnew);
            row_max[i] = mnew;
            float p0 = __expf(sacc[i][0] - mnew);
            float p1 = __expf(sacc[i][1] - mnew);
            float p2 = __expf(sacc[i][2] - mnew);
            float p3 = __expf(sacc[i][3] - mnew);
            float ps = (p0 + p1) + (p2 + p3);
            #pragma unroll
            for (int off = 8; off >= 1; off >>= 1)
                ps += __shfl_xor_sync(0xffffffffu, ps, off);
            row_l[i] = row_l[i] * corr + ps;
            #pragma unroll
            for (int j = 0; j < 4; j++) o_acc[i][j] *= corr;
            *(float4*)&Ps[mrow*PROW + tx*4] = make_float4(p0, p1, p2, p3);
        }
        __syncthreads();

        // GEMM2: O += P V. Process 4 keys at a time; V fragment loaded first
        // to bound register pressure.
        #pragma unroll
        for (int n0 = 0; n0 < BN; n0 += 4) {
            float bv[4][4];
            #pragma unroll
            for (int q = 0; q < 4; q++)
                *(float4*)&bv[q][0] = *(const float4*)&Vs[(n0+q)*KROW + tx*4];
            #pragma unroll
            for (int i = 0; i < 8; i++) {
                float4 a4 = *(const float4*)&Ps[(ty*8 + i)*PROW + n0];
                float av[4] = {a4.x, a4.y, a4.z, a4.w};
                #pragma unroll
                for (int q = 0; q < 4; q++)
                    #pragma unroll
                    for (int j = 0; j < 4; j++)
                        o_acc[i][j] = fmaf(av[q], bv[q][j], o_acc[i][j]);
            }
        }
        __syncthreads();
    }

    // Write normalized output: g_lin[(b*S + s)*D + h*HD + d]
    const int b = bh >> 4, h = bh & 15;
    #pragma unroll
    for (int i = 0; i < 8; i++) {
        float inv = 1.0f / row_l[i];
        float4 o = make_float4(o_acc[i][0]*inv, o_acc[i][1]*inv,
                               o_acc[i][2]*inv, o_acc[i][3]*inv);
        *(float4*)(g_lin + ((size_t)(b * SS + s0 + ty*8 + i)) * DM + h * HD + tx*4) = o;
    }
}

// ---------------------------------------------------------------------------
extern "C" void kernel_launch(void* const* d_in, const int* in_sizes, int n_in,
                              void* d_out, int out_size)
{
    const float* x  = (const float*)d_in[0];
    const int*  pos = (const int*)  d_in[1];
    const float* wq = (const float*)d_in[2];
    const float* wk = (const float*)d_in[3];
    const float* wv = (const float*)d_in[4];
    const float* wo = (const float*)d_in[5];
    float* out = (float*)d_out;

    void* lin_p = nullptr;
    cudaGetSymbolAddress(&lin_p, g_lin);
    float* lin = (float*)lin_p;

    cudaFuncSetAttribute(attn_fwd, cudaFuncAttributeMaxDynamicSharedMemorySize, ATTN_SMEM);

    // 1) q,k,v = x @ {wq,wk,wv}^T
    gemm_xwT<<<dim3(DM/128, MT/128, 3), 256>>>(x, wq, wk, wv, lin);

    // 2) RoPE + head split
    const int total = 3 * BB * SS * NH * (HD/2);
    rope_split<<<(total + 255) / 256, 256>>>(pos);

    // 3) causal attention (writes back into g_lin in [b,s,D] layout)
    attn_fwd<<<dim3(SS/BM, BB*NH), 256, ATTN_SMEM>>>();

    // 4) out = attn @ wo^T
    gemm_xwT<<<dim3(DM/128, MT/128, 1), 256>>>(lin, wo, wo, wo, out);
}

// round 5
// speedup vs baseline: 1.7080x; 1.6485x over previous
#include <cuda_runtime.h>
#include <cuda_bf16.h>
#include <math.h>
#include <stdint.h>

#define BB 4
#define SS 2048
#define DM 1024
#define NH 16
#define HD 64
#define MT (BB*SS)          // 8192 rows
#define BSD (MT*DM)         // 8,388,608 elements per matrix

// Scratch (static device globals: allowed; no runtime allocation)
static __device__ float g_lin[3*BSD];    // qkv fp32 outputs; slot 0 reused for attn output
static __device__ float g_heads[3*BSD];  // q,k,v in [b,h,s,d] layout (q,k RoPE'd)
static __device__ __align__(16) __nv_bfloat16 g_xhi[BSD];
static __device__ __align__(16) __nv_bfloat16 g_xlo[BSD];
static __device__ __align__(16) __nv_bfloat16 g_whi[4*DM*DM];
static __device__ __align__(16) __nv_bfloat16 g_wlo[4*DM*DM];

// ---------------------------------------------------------------------------
// PTX helpers (compute_103-baseline only: mma.sync / ldmatrix / cp.async)
// ---------------------------------------------------------------------------
__device__ __forceinline__ uint32_t smem_u32(const void* p) {
    uint32_t a;
    asm("{ .reg .u64 t; cvta.to.shared.u64 t, %1; cvt.u32.u64 %0, t; }" : "=r"(a) : "l"(p));
    return a;
}
__device__ __forceinline__ void cp16(uint32_t saddr, const void* g) {
    asm volatile("cp.async.cg.shared.global [%0], [%1], 16;" :: "r"(saddr), "l"(g) : "memory");
}
__device__ __forceinline__ void cp_commit() {
    asm volatile("cp.async.commit_group;" ::: "memory");
}
template <int N>
__device__ __forceinline__ void cp_wait() {
    asm volatile("cp.async.wait_group %0;" :: "n"(N) : "memory");
}
__device__ __forceinline__ void ldsm4(uint32_t addr, uint32_t r[4]) {
    asm volatile("ldmatrix.sync.aligned.m8n8.x4.shared.b16 {%0,%1,%2,%3}, [%4];"
                 : "=r"(r[0]), "=r"(r[1]), "=r"(r[2]), "=r"(r[3]) : "r"(addr));
}
__device__ __forceinline__ void mma16816(float c[4], const uint32_t a[4],
                                         uint32_t b0, uint32_t b1) {
    asm volatile(
        "mma.sync.aligned.m16n8k16.row.col.f32.bf16.bf16.f32 "
        "{%0,%1,%2,%3}, {%4,%5,%6,%7}, {%8,%9}, {%0,%1,%2,%3};"
        : "+f"(c[0]), "+f"(c[1]), "+f"(c[2]), "+f"(c[3])
        : "r"(a[0]), "r"(a[1]), "r"(a[2]), "r"(a[3]), "r"(b0), "r"(b1));
}
#define SWZ(off) ((off) ^ (((off) >> 3) & 0x70))

// ---------------------------------------------------------------------------
// fp32 -> bf16 (hi, lo) split conversion.  n4 = elems/4.
// ---------------------------------------------------------------------------
__global__ void conv_hilo(const float4* __restrict__ src,
                          __nv_bfloat16* __restrict__ hi,
                          __nv_bfloat16* __restrict__ lo, int n4)
{
    int i = blockIdx.x * blockDim.x + threadIdx.x;
    if (i >= n4) return;
    float4 v = src[i];
    float f[4] = {v.x, v.y, v.z, v.w};
    __nv_bfloat162 h2[2], l2[2];
    #pragma unroll
    for (int j = 0; j < 2; j++) {
        __nv_bfloat16 h0 = __float2bfloat16_rn(f[2*j]);
        __nv_bfloat16 h1 = __float2bfloat16_rn(f[2*j+1]);
        __nv_bfloat16 l0 = __float2bfloat16_rn(f[2*j]   - __bfloat162float(h0));
        __nv_bfloat16 l1 = __float2bfloat16_rn(f[2*j+1] - __bfloat162float(h1));
        h2[j] = __nv_bfloat162(h0, h1);
        l2[j] = __nv_bfloat162(l0, l1);
    }
    *(uint2*)(hi + 4*(size_t)i) = *(uint2*)h2;
    *(uint2*)(lo + 4*(size_t)i) = *(uint2*)l2;
}

// ---------------------------------------------------------------------------
// HMMA split-bf16 GEMM: C[m][n] = sum_k A[m][k] * W[n][k]
// 128x128 CTA tile, 512 threads (16 warps, 4x4), warp tile 32x32.
// K-chunk 64, SW128 smem, cp.async double buffer.
// Per k16: 3 MMA terms (Ahi*Bhi + Ahi*Blo + Alo*Bhi) -> fp32 acc in regs.
// ---------------------------------------------------------------------------
#define GK_TILE  16384                  // 128 rows x 128B (64 bf16)
#define GK_STAGE (4*GK_TILE)            // Ahi, Alo, Bhi, Blo
#define GK_SMEM  (2*GK_STAGE)           // double buffered
#define NKCH     16                     // 1024 / 64

__global__ void __launch_bounds__(512, 1) gemm_hmma(
    const __nv_bfloat16* __restrict__ Ahi, const __nv_bfloat16* __restrict__ Alo,
    const __nv_bfloat16* __restrict__ Whi, const __nv_bfloat16* __restrict__ Wlo,
    float* __restrict__ C)
{
    extern __shared__ char smem[];
    const uint32_t sbase = smem_u32(smem);
    const int tid = threadIdx.x, lane = tid & 31, wid = tid >> 5;
    const int n0 = blockIdx.x * 128, m0 = blockIdx.y * 128, z = blockIdx.z;

    const __nv_bfloat16* __restrict__ srcs[4] = {
        Ahi + (size_t)m0 * DM,
        Alo + (size_t)m0 * DM,
        Whi + (size_t)z * DM * DM + (size_t)n0 * DM,
        Wlo + (size_t)z * DM * DM + (size_t)n0 * DM };
    float* Cp = C + (size_t)z * BSD;

    // per-thread fill coordinates: 2 x 16B units per tile
    const int f_row0 = tid >> 3;              // unit 0: row 0..63
    const int f_cu   = tid & 7;               // 16B column unit 0..7
    const uint32_t f_off0 = SWZ((uint32_t)(f_row0        * 128 + f_cu * 16));
    const uint32_t f_off1 = SWZ((uint32_t)((f_row0 + 64) * 128 + f_cu * 16));

    auto fill = [&](int st, int kt) {
        uint32_t sb = sbase + st * GK_STAGE;
        #pragma unroll
        for (int t = 0; t < 4; t++) {
            const __nv_bfloat16* s = srcs[t] + kt * 64 + f_cu * 8;
            cp16(sb + t * GK_TILE + f_off0, s + (size_t)f_row0 * DM);
            cp16(sb + t * GK_TILE + f_off1, s + (size_t)(f_row0 + 64) * DM);
        }
        cp_commit();
    };

    // warp tile position
    const int wm = (wid & 3) * 32;            // m offset in tile
    const int wn = (wid >> 2) * 32;           // n offset in tile
    // per-lane ldmatrix address components
    const int a_row = lane & 15;
    const int a_ku  = lane >> 4;
    const int b_row = ((lane >> 4) << 3) + (lane & 7);
    const int b_ku  = (lane >> 3) & 1;

    float acc[2][4][4];
    #pragma unroll
    for (int i = 0; i < 2; i++)
        #pragma unroll
        for (int j = 0; j < 4; j++)
            #pragma unroll
            for (int c = 0; c < 4; c++) acc[i][j][c] = 0.0f;

    fill(0, 0);
    fill(1, 1);

    #pragma unroll 1
    for (int kt = 0; kt < NKCH; kt++) {
        if (kt == NKCH - 1) cp_wait<0>(); else cp_wait<1>();
        __syncthreads();

        const uint32_t sb  = sbase + (kt & 1) * GK_STAGE;
        const uint32_t sAh = sb, sAl = sb + GK_TILE;
        const uint32_t sBh = sb + 2*GK_TILE, sBl = sb + 3*GK_TILE;

        #pragma unroll
        for (int q = 0; q < 4; q++) {          // k16 step within chunk
            const int cu = q * 2;
            uint32_t ah[2][4], al[2][4], bh[2][4], bl[2][4];
            #pragma unroll
            for (int i = 0; i < 2; i++) {       // m-atoms at wm, wm+16
                uint32_t off = SWZ((uint32_t)((wm + i*16 + a_row) * 128 + (cu + a_ku) * 16));
                ldsm4(sAh + off, ah[i]);
                ldsm4(sAl + off, al[i]);
            }
            #pragma unroll
            for (int j = 0; j < 2; j++) {       // n16 groups at wn, wn+16
                uint32_t off = SWZ((uint32_t)((wn + j*16 + b_row) * 128 + (cu + b_ku) * 16));
                ldsm4(sBh + off, bh[j]);
                ldsm4(sBl + off, bl[j]);
            }
            #pragma unroll
            for (int i = 0; i < 2; i++)
                #pragma unroll
                for (int jj = 0; jj < 4; jj++) {   // n-atoms 0,8,16,24
                    const int j16 = jj >> 1, h = (jj & 1) * 2;
                    mma16816(acc[i][jj], ah[i], bh[j16][h], bh[j16][h+1]);
                    mma16816(acc[i][jj], ah[i], bl[j16][h], bl[j16][h+1]);
                    mma16816(acc[i][jj], al[i], bh[j16][h], bh[j16][h+1]);
                }
        }
        __syncthreads();
        if (kt + 2 < NKCH) fill(kt & 1, kt + 2);
    }

    // Epilogue: direct float2 stores
    const int er = lane >> 2;           // 0..7
    const int ec = (lane & 3) * 2;
    #pragma unroll
    for (int i = 0; i < 2; i++)
        #pragma unroll
        for (int jj = 0; jj < 4; jj++) {
            const int row = m0 + wm + i*16 + er;
            const int col = n0 + wn + jj*8 + ec;
            *(float2*)(Cp + (size_t)row * DM + col)       = make_float2(acc[i][jj][0], acc[i][jj][1]);
            *(float2*)(Cp + (size_t)(row + 8) * DM + col) = make_float2(acc[i][jj][2], acc[i][jj][3]);
        }
}

// ---------------------------------------------------------------------------
// RoPE + head split: g_lin[mat][b*S+s][D] -> g_heads[mat][b*H+h][s][HD]
// ---------------------------------------------------------------------------
__global__ void rope_split(const int* __restrict__ pos)
{
    const int total = 3 * BB * SS * NH * (HD/2);
    int i = blockIdx.x * blockDim.x + threadIdx.x;
    if (i >= total) return;

    int p = i & 31;  int t = i >> 5;
    int h = t & (NH - 1);   t >>= 4;
    int s = t & (SS - 1);   t >>= 11;
    int b = t & (BB - 1);   int mat = t >> 2;

    const float* src = g_lin + (size_t)mat * BSD + (size_t)(b * SS + s) * DM + h * HD + 2 * p;
    float e = src[0], o = src[1];

    if (mat < 2) {
        int   ps  = pos[b * SS + s];
        float ifr = __expf(-((float)(2 * p) * (1.0f / HD)) * 9.210340371976184f);
        float ang = (float)ps * ifr;
        float sn, cs;
        sincosf(ang, &sn, &cs);
        float e2 = e * cs - o * sn;
        o        = e * sn + o * cs;
        e = e2;
    }

    float* dst = g_heads + (size_t)mat * BSD + ((size_t)(b * NH + h) * SS + s) * HD + 2 * p;
    dst[0] = e; dst[1] = o;
}

// ---------------------------------------------------------------------------
// Streaming causal attention (round-2 version, unchanged)
// ---------------------------------------------------------------------------
#define BM 128
#define BN 64
#define QROW 136
#define KROW 68
#define PROW 68
#define ATTN_SMEM ((64*QROW + 64*KROW + 64*KROW + BM*PROW) * 4)

__global__ void __launch_bounds__(256, 2) attn_fwd()
{
    extern __shared__ float sm[];
    float* Qs = sm;
    float* Ks = Qs + 64*QROW;
    float* Vs = Ks + 64*KROW;
    float* Ps = Vs + 64*KROW;

    const int tid = threadIdx.x;
    const int tx = tid & 15, ty = tid >> 4;
    const int qt = (int)gridDim.x - 1 - (int)blockIdx.x;
    const int bh = blockIdx.y;
    const int s0 = qt * BM;

    const float* Qg = g_heads +                 ((size_t)bh * SS + s0) * HD;
    const float* Kg = g_heads + (size_t)BSD   + (size_t)bh * SS * HD;
    const float* Vg = g_heads + 2*(size_t)BSD + (size_t)bh * SS * HD;

    {
        int m  = tid >> 1;
        int c0 = (tid & 1) * 32;
        #pragma unroll
        for (int r = 0; r < 8; r++) {
            int d = c0 + r * 4;
            float4 v = *(const float4*)(Qg + (size_t)m * HD + d);
            Qs[(d+0)*QROW + m] = v.x; Qs[(d+1)*QROW + m] = v.y;
            Qs[(d+2)*QROW + m] = v.z; Qs[(d+3)*QROW + m] = v.w;
        }
    }

    float o_acc[8][4];
    float row_max[8], row_l[8];
    #pragma unroll
    for (int i = 0; i < 8; i++) {
        row_max[i] = -1e30f; row_l[i] = 0.0f;
        #pragma unroll
        for (int j = 0; j < 4; j++) o_acc[i][j] = 0.0f;
    }

    const float scale = 0.125f;
    const int nkt = 2 * qt + 2;

    for (int kb = 0; kb < nkt; kb++) {
        {
            const float* kg = Kg + (size_t)kb * BN * HD;
            const float* vg = Vg + (size_t)kb * BN * HD;
            int n  = tid >> 2;
            int d0 = (tid & 3) * 16;
            #pragma unroll
            for (int r = 0; r < 4; r++) {
                int d = d0 + r * 4;
                float4 kv = *(const float4*)(kg + (size_t)n * HD + d);
                Ks[(d+0)*KROW + n] = kv.x; Ks[(d+1)*KROW + n] = kv.y;
                Ks[(d+2)*KROW + n] = kv.z; Ks[(d+3)*KROW + n] = kv.w;
                float4 vv = *(const float4*)(vg + (size_t)n * HD + d);
                *(float4*)&Vs[n*KROW + d] = vv;
            }
        }
        __syncthreads();

        float sacc[8][4];
        #pragma unroll
        for (int i = 0; i < 8; i++)
            #pragma unroll
            for (int j = 0; j < 4; j++) sacc[i][j] = 0.0f;

        #pragma unroll
        for (int d = 0; d < 64; d++) {
            float a[8];
            *(float4*)&a[0] = *(const float4*)&Qs[d*QROW + ty*8];
            *(float4*)&a[4] = *(const float4*)&Qs[d*QROW + ty*8 + 4];
            float4 bq = *(const float4*)&Ks[d*KROW + tx*4];
            float b[4] = {bq.x, bq.y, bq.z, bq.w};
            #pragma unroll
            for (int i = 0; i < 8; i++)
                #pragma unroll
                for (int j = 0; j < 4; j++)
                    sacc[i][j] = fmaf(a[i], b[j], sacc[i][j]);
        }

        const bool tilemask = (kb >= 2 * qt);
        const int noff = kb * BN - s0;
        #pragma unroll
        for (int i = 0; i < 8; i++) {
            const int mrow = ty * 8 + i;
            float mx = -1e30f;
            #pragma unroll
            for (int j = 0; j < 4; j++) {
                float sv = sacc[i][j] * scale;
                if (tilemask && (noff + tx*4 + j > mrow)) sv = -1e30f;
                sacc[i][j] = sv;
                mx = fmaxf(mx, sv);
            }
            #pragma unroll
            for (int off = 8; off >= 1; off >>= 1)
                mx = fmaxf(mx, __shfl_xor_sync(0xffffffffu, mx, off));
            float mnew = fmaxf(row_max[i], mx);
            float corr = __expf(row_max[i] - mnew);
            row_max[i] = mnew;
            float p0 = __expf(sacc[i][0] - mnew);
            float p1 = __expf(sacc[i][1] - mnew);
            float p2 = __expf(sacc[i][2] - mnew);
            float p3 = __expf(sacc[i][3] - mnew);
            float ps = (p0 + p1) + (p2 + p3);
            #pragma unroll
            for (int off = 8; off >= 1; off >>= 1)
                ps += __shfl_xor_sync(0xffffffffu, ps, off);
            row_l[i] = row_l[i] * corr + ps;
            #pragma unroll
            for (int j = 0; j < 4; j++) o_acc[i][j] *= corr;
            *(float4*)&Ps[mrow*PROW + tx*4] = make_float4(p0, p1, p2, p3);
        }
        __syncthreads();

        #pragma unroll
        for (int n0 = 0; n0 < BN; n0 += 4) {
            float bv[4][4];
            #pragma unroll
            for (int q = 0; q < 4; q++)
                *(float4*)&bv[q][0] = *(const float4*)&Vs[(n0+q)*KROW + tx*4];
            #pragma unroll
            for (int i = 0; i < 8; i++) {
                float4 a4 = *(const float4*)&Ps[(ty*8 + i)*PROW + n0];
                float av[4] = {a4.x, a4.y, a4.z, a4.w};
                #pragma unroll
                for (int q = 0; q < 4; q++)
                    #pragma unroll
                    for (int j = 0; j < 4; j++)
                        o_acc[i][j] = fmaf(av[q], bv[q][j], o_acc[i][j]);
            }
        }
        __syncthreads();
    }

    const int b = bh >> 4, h = bh & 15;
    #pragma unroll
    for (int i = 0; i < 8; i++) {
        float inv = 1.0f / row_l[i];
        float4 o = make_float4(o_acc[i][0]*inv, o_acc[i][1]*inv,
                               o_acc[i][2]*inv, o_acc[i][3]*inv);
        *(float4*)(g_lin + ((size_t)(b * SS + s0 + ty*8 + i)) * DM + h * HD + tx*4) = o;
    }
}

// ---------------------------------------------------------------------------
extern "C" void kernel_launch(void* const* d_in, const int* in_sizes, int n_in,
                              void* d_out, int out_size)
{
    const float* x  = (const float*)d_in[0];
    const int*  pos = (const int*)  d_in[1];
    const float* w[4] = { (const float*)d_in[2], (const float*)d_in[3],
                          (const float*)d_in[4], (const float*)d_in[5] };
    float* out = (float*)d_out;

    void* p;
    cudaGetSymbolAddress(&p, g_lin);   float* lin = (float*)p;
    cudaGetSymbolAddress(&p, g_xhi);   __nv_bfloat16* xhi = (__nv_bfloat16*)p;
    cudaGetSymbolAddress(&p, g_xlo);   __nv_bfloat16* xlo = (__nv_bfloat16*)p;
    cudaGetSymbolAddress(&p, g_whi);   __nv_bfloat16* whi = (__nv_bfloat16*)p;
    cudaGetSymbolAddress(&p, g_wlo);   __nv_bfloat16* wlo = (__nv_bfloat16*)p;

    cudaFuncSetAttribute(attn_fwd,  cudaFuncAttributeMaxDynamicSharedMemorySize, ATTN_SMEM);
    cudaFuncSetAttribute(gemm_hmma, cudaFuncAttributeMaxDynamicSharedMemorySize, GK_SMEM);

    // 0) split-convert x and weights to bf16 hi/lo
    conv_hilo<<<(BSD/4 + 255)/256, 256>>>((const float4*)x, xhi, xlo, BSD/4);
    for (int z = 0; z < 4; z++)
        conv_hilo<<<(DM*DM/4 + 255)/256, 256>>>((const float4*)w[z],
                                                whi + (size_t)z*DM*DM,
                                                wlo + (size_t)z*DM*DM, DM*DM/4);

    // 1) q,k,v = x @ {wq,wk,wv}^T  (HMMA, split bf16)
    gemm_hmma<<<dim3(DM/128, MT/128, 3), 512, GK_SMEM>>>(xhi, xlo, whi, wlo, lin);

    // 2) RoPE + head split
    const int total = 3 * BB * SS * NH * (HD/2);
    rope_split<<<(total + 255) / 256, 256>>>(pos);

    // 3) causal attention -> g_lin (fp32, [b,s,D])
    attn_fwd<<<dim3(SS/BM, BB*NH), 256, ATTN_SMEM>>>();

    // 4) split-convert attention output, then out = attn @ wo^T
    conv_hilo<<<(BSD/4 + 255)/256, 256>>>((const float4*)lin, xhi, xlo, BSD/4);
    gemm_hmma<<<dim3(DM/128, MT/128, 1), 512, GK_SMEM>>>(xhi, xlo,
                                                         whi + 3*(size_t)DM*DM,
                                                         wlo + 3*(size_t)DM*DM, out);
}

// round 6
// speedup vs baseline: 3.0731x; 1.7993x over previous
#include <cuda_runtime.h>
#include <cuda_bf16.h>
#include <math.h>
#include <stdint.h>

#define BB 4
#define SS 2048
#define DM 1024
#define NH 16
#define HD 64
#define MT (BB*SS)          // 8192 rows
#define BSD (MT*DM)         // 8,388,608 elements per matrix

// Scratch (static device globals)
static __device__ float g_lin[3*BSD];                       // qkv fp32
static __device__ __align__(16) __nv_bfloat16 g_xhi[BSD];   // x hi / attn-out hi
static __device__ __align__(16) __nv_bfloat16 g_xlo[BSD];
static __device__ __align__(16) __nv_bfloat16 g_whi[4*DM*DM];
static __device__ __align__(16) __nv_bfloat16 g_wlo[4*DM*DM];
static __device__ __align__(16) __nv_bfloat16 g_qhi[BSD], g_qlo[BSD];
static __device__ __align__(16) __nv_bfloat16 g_khi[BSD], g_klo[BSD];
static __device__ __align__(16) __nv_bfloat16 g_vhi[BSD], g_vlo[BSD];

// ---------------------------------------------------------------------------
// PTX helpers (compute_103 baseline: mma.sync / ldmatrix / cp.async)
// ---------------------------------------------------------------------------
__device__ __forceinline__ uint32_t smem_u32(const void* p) {
    uint32_t a;
    asm("{ .reg .u64 t; cvta.to.shared.u64 t, %1; cvt.u32.u64 %0, t; }" : "=r"(a) : "l"(p));
    return a;
}
__device__ __forceinline__ void cp16(uint32_t saddr, const void* g) {
    asm volatile("cp.async.cg.shared.global [%0], [%1], 16;" :: "r"(saddr), "l"(g) : "memory");
}
__device__ __forceinline__ void cp_commit() {
    asm volatile("cp.async.commit_group;" ::: "memory");
}
template <int N>
__device__ __forceinline__ void cp_wait() {
    asm volatile("cp.async.wait_group %0;" :: "n"(N) : "memory");
}
__device__ __forceinline__ void ldsm4(uint32_t addr, uint32_t r[4]) {
    asm volatile("ldmatrix.sync.aligned.m8n8.x4.shared.b16 {%0,%1,%2,%3}, [%4];"
                 : "=r"(r[0]), "=r"(r[1]), "=r"(r[2]), "=r"(r[3]) : "r"(addr));
}
__device__ __forceinline__ void ldsm4t(uint32_t addr, uint32_t r[4]) {
    asm volatile("ldmatrix.sync.aligned.m8n8.x4.trans.shared.b16 {%0,%1,%2,%3}, [%4];"
                 : "=r"(r[0]), "=r"(r[1]), "=r"(r[2]), "=r"(r[3]) : "r"(addr));
}
__device__ __forceinline__ void mma16816(float c[4], const uint32_t a[4],
                                         uint32_t b0, uint32_t b1) {
    asm volatile(
        "mma.sync.aligned.m16n8k16.row.col.f32.bf16.bf16.f32 "
        "{%0,%1,%2,%3}, {%4,%5,%6,%7}, {%8,%9}, {%0,%1,%2,%3};"
        : "+f"(c[0]), "+f"(c[1]), "+f"(c[2]), "+f"(c[3])
        : "r"(a[0]), "r"(a[1]), "r"(a[2]), "r"(a[3]), "r"(b0), "r"(b1));
}
#define SWZ(off) ((off) ^ (((off) >> 3) & 0x70))

__device__ __forceinline__ uint32_t pack_bf16(float x, float y) {
    __nv_bfloat162 t(__float2bfloat16_rn(x), __float2bfloat16_rn(y));
    return *(uint32_t*)&t;
}

// ---------------------------------------------------------------------------
// fp32 -> bf16 (hi, lo) split conversion.  n4 = elems/4.
// ---------------------------------------------------------------------------
__global__ void conv_hilo(const float4* __restrict__ src,
                          __nv_bfloat16* __restrict__ hi,
                          __nv_bfloat16* __restrict__ lo, int n4)
{
    int i = blockIdx.x * blockDim.x + threadIdx.x;
    if (i >= n4) return;
    float4 v = src[i];
    float f[4] = {v.x, v.y, v.z, v.w};
    __nv_bfloat162 h2[2], l2[2];
    #pragma unroll
    for (int j = 0; j < 2; j++) {
        __nv_bfloat16 h0 = __float2bfloat16_rn(f[2*j]);
        __nv_bfloat16 h1 = __float2bfloat16_rn(f[2*j+1]);
        __nv_bfloat16 l0 = __float2bfloat16_rn(f[2*j]   - __bfloat162float(h0));
        __nv_bfloat16 l1 = __float2bfloat16_rn(f[2*j+1] - __bfloat162float(h1));
        h2[j] = __nv_bfloat162(h0, h1);
        l2[j] = __nv_bfloat162(l0, l1);
    }
    *(uint2*)(hi + 4*(size_t)i) = *(uint2*)h2;
    *(uint2*)(lo + 4*(size_t)i) = *(uint2*)l2;
}

// ---------------------------------------------------------------------------
// HMMA split-bf16 GEMM (verified round-5 version, unchanged)
// ---------------------------------------------------------------------------
#define GK_TILE  16384
#define GK_STAGE (4*GK_TILE)
#define GK_SMEM  (2*GK_STAGE)
#define NKCH     16

__global__ void __launch_bounds__(512, 1) gemm_hmma(
    const __nv_bfloat16* __restrict__ Ahi, const __nv_bfloat16* __restrict__ Alo,
    const __nv_bfloat16* __restrict__ Whi, const __nv_bfloat16* __restrict__ Wlo,
    float* __restrict__ C)
{
    extern __shared__ char smem[];
    const uint32_t sbase = smem_u32(smem);
    const int tid = threadIdx.x, lane = tid & 31, wid = tid >> 5;
    const int n0 = blockIdx.x * 128, m0 = blockIdx.y * 128, z = blockIdx.z;

    const __nv_bfloat16* __restrict__ srcs[4] = {
        Ahi + (size_t)m0 * DM,
        Alo + (size_t)m0 * DM,
        Whi + (size_t)z * DM * DM + (size_t)n0 * DM,
        Wlo + (size_t)z * DM * DM + (size_t)n0 * DM };
    float* Cp = C + (size_t)z * BSD;

    const int f_row0 = tid >> 3;
    const int f_cu   = tid & 7;
    const uint32_t f_off0 = SWZ((uint32_t)(f_row0        * 128 + f_cu * 16));
    const uint32_t f_off1 = SWZ((uint32_t)((f_row0 + 64) * 128 + f_cu * 16));

    auto fill = [&](int st, int kt) {
        uint32_t sb = sbase + st * GK_STAGE;
        #pragma unroll
        for (int t = 0; t < 4; t++) {
            const __nv_bfloat16* s = srcs[t] + kt * 64 + f_cu * 8;
            cp16(sb + t * GK_TILE + f_off0, s + (size_t)f_row0 * DM);
            cp16(sb + t * GK_TILE + f_off1, s + (size_t)(f_row0 + 64) * DM);
        }
        cp_commit();
    };

    const int wm = (wid & 3) * 32;
    const int wn = (wid >> 2) * 32;
    const int a_row = lane & 15;
    const int a_ku  = lane >> 4;
    const int b_row = ((lane >> 4) << 3) + (lane & 7);
    const int b_ku  = (lane >> 3) & 1;

    float acc[2][4][4];
    #pragma unroll
    for (int i = 0; i < 2; i++)
        #pragma unroll
        for (int j = 0; j < 4; j++)
            #pragma unroll
            for (int c = 0; c < 4; c++) acc[i][j][c] = 0.0f;

    fill(0, 0);
    fill(1, 1);

    #pragma unroll 1
    for (int kt = 0; kt < NKCH; kt++) {
        if (kt == NKCH - 1) cp_wait<0>(); else cp_wait<1>();
        __syncthreads();

        const uint32_t sb  = sbase + (kt & 1) * GK_STAGE;
        const uint32_t sAh = sb, sAl = sb + GK_TILE;
        const uint32_t sBh = sb + 2*GK_TILE, sBl = sb + 3*GK_TILE;

        #pragma unroll
        for (int q = 0; q < 4; q++) {
            const int cu = q * 2;
            uint32_t ah[2][4], al[2][4], bh[2][4], bl[2][4];
            #pragma unroll
            for (int i = 0; i < 2; i++) {
                uint32_t off = SWZ((uint32_t)((wm + i*16 + a_row) * 128 + (cu + a_ku) * 16));
                ldsm4(sAh + off, ah[i]);
                ldsm4(sAl + off, al[i]);
            }
            #pragma unroll
            for (int j = 0; j < 2; j++) {
                uint32_t off = SWZ((uint32_t)((wn + j*16 + b_row) * 128 + (cu + b_ku) * 16));
                ldsm4(sBh + off, bh[j]);
                ldsm4(sBl + off, bl[j]);
            }
            #pragma unroll
            for (int i = 0; i < 2; i++)
                #pragma unroll
                for (int jj = 0; jj < 4; jj++) {
                    const int j16 = jj >> 1, h = (jj & 1) * 2;
                    mma16816(acc[i][jj], ah[i], bh[j16][h], bh[j16][h+1]);
                    mma16816(acc[i][jj], ah[i], bl[j16][h], bl[j16][h+1]);
                    mma16816(acc[i][jj], al[i], bh[j16][h], bh[j16][h+1]);
                }
        }
        __syncthreads();
        if (kt + 2 < NKCH) fill(kt & 1, kt + 2);
    }

    const int er = lane >> 2;
    const int ec = (lane & 3) * 2;
    #pragma unroll
    for (int i = 0; i < 2; i++)
        #pragma unroll
        for (int jj = 0; jj < 4; jj++) {
            const int row = m0 + wm + i*16 + er;
            const int col = n0 + wn + jj*8 + ec;
            *(float2*)(Cp + (size_t)row * DM + col)       = make_float2(acc[i][jj][0], acc[i][jj][1]);
            *(float2*)(Cp + (size_t)(row + 8) * DM + col) = make_float2(acc[i][jj][2], acc[i][jj][3]);
        }
}

// ---------------------------------------------------------------------------
// RoPE + head split + bf16 hi/lo: g_lin[mat] -> g_{q,k,v}{hi,lo} [bh][s][d]
// ---------------------------------------------------------------------------
__global__ void rope_split_bf16(const int* __restrict__ pos)
{
    const int total = 3 * BB * SS * NH * (HD/2);
    int i = blockIdx.x * blockDim.x + threadIdx.x;
    if (i >= total) return;

    int p = i & 31;  int t = i >> 5;
    int h = t & (NH - 1);   t >>= 4;
    int s = t & (SS - 1);   t >>= 11;
    int b = t & (BB - 1);   int mat = t >> 2;

    const float* src = g_lin + (size_t)mat * BSD + (size_t)(b * SS + s) * DM + h * HD + 2 * p;
    float e = src[0], o = src[1];

    if (mat < 2) {
        int   ps  = pos[b * SS + s];
        float ifr = __expf(-((float)(2 * p) * (1.0f / HD)) * 9.210340371976184f);
        float ang = (float)ps * ifr;
        float sn, cs;
        sincosf(ang, &sn, &cs);
        float e2 = e * cs - o * sn;
        o        = e * sn + o * cs;
        e = e2;
    }

    __nv_bfloat16 ehi = __float2bfloat16_rn(e);
    __nv_bfloat16 ohi = __float2bfloat16_rn(o);
    __nv_bfloat16 elo = __float2bfloat16_rn(e - __bfloat162float(ehi));
    __nv_bfloat16 olo = __float2bfloat16_rn(o - __bfloat162float(ohi));
    __nv_bfloat162 hi2(ehi, ohi), lo2(elo, olo);

    size_t di = ((size_t)(b * NH + h) * SS + s) * HD + 2 * p;
    __nv_bfloat16* hiA = (mat == 0) ? g_qhi : (mat == 1 ? g_khi : g_vhi);
    __nv_bfloat16* loA = (mat == 0) ? g_qlo : (mat == 1 ? g_klo : g_vlo);
    *(uint32_t*)(hiA + di) = *(uint32_t*)&hi2;
    *(uint32_t*)(loA + di) = *(uint32_t*)&lo2;
}

// ---------------------------------------------------------------------------
// HMMA flash attention: 128 query rows per CTA, 8 warps (16 rows each),
// key tiles of 64.  Split-bf16 for S=QK^T and O=PV; P stays in registers.
// smem: Qhi/Qlo [128][64] (16KB ea) + double-buffered K/V hi/lo (32KB/stage).
// Output written as bf16 hi/lo directly into g_xhi/g_xlo ([b][s][D]).
// ---------------------------------------------------------------------------
#define AQ_TILE 16384
#define AKV_TILE 8192
#define AKV_STAGE (4*AKV_TILE)
#define ASMEM (2*AQ_TILE + 2*AKV_STAGE)   // 96KB

__global__ void __launch_bounds__(256, 1) attn_hmma()
{
    extern __shared__ char smem[];
    const uint32_t sbase = smem_u32(smem);
    const int tid = threadIdx.x, lane = tid & 31, wid = tid >> 5;
    const int qt = (int)gridDim.x - 1 - (int)blockIdx.x;
    const int bh = blockIdx.y;
    const int s0 = qt * 128;
    const int nkt = 2 * qt + 2;

    const size_t bhoff = (size_t)bh * SS * HD;
    const __nv_bfloat16* Qh = g_qhi + bhoff + (size_t)s0 * HD;
    const __nv_bfloat16* Ql = g_qlo + bhoff + (size_t)s0 * HD;
    const __nv_bfloat16* kvsrc[4] = { g_khi + bhoff, g_klo + bhoff,
                                      g_vhi + bhoff, g_vlo + bhoff };

    const uint32_t sQ  = sbase;
    const uint32_t sKV = sbase + 2*AQ_TILE;

    // ---- async fills ----
    {   // Q: 2 tiles x 128 rows x 8 units
        #pragma unroll
        for (int j = 0; j < 4; j++) {
            int idx = j * 256 + tid;
            int row = idx >> 3, cu = idx & 7;
            uint32_t off = SWZ((uint32_t)(row * 128 + cu * 16));
            cp16(sQ + off,           Qh + (size_t)row * HD + cu * 8);
            cp16(sQ + AQ_TILE + off, Ql + (size_t)row * HD + cu * 8);
        }
        cp_commit();
    }
    auto fill_kv = [&](int st, int kb) {
        uint32_t sb = sKV + st * AKV_STAGE;
        #pragma unroll
        for (int t = 0; t < 4; t++) {
            const __nv_bfloat16* s = kvsrc[t] + (size_t)kb * 64 * HD;
            #pragma unroll
            for (int r = 0; r < 2; r++) {
                int idx = r * 256 + tid;
                int row = idx >> 3, cu = idx & 7;
                cp16(sb + t * AKV_TILE + SWZ((uint32_t)(row * 128 + cu * 16)),
                     s + (size_t)row * HD + cu * 8);
            }
        }
        cp_commit();
    };
    fill_kv(0, 0);
    fill_kv(1, 1);

    // ---- Q fragments into registers (4 k16 steps, hi+lo) ----
    cp_wait<2>();
    __syncthreads();
    uint32_t qh[4][4], ql[4][4];
    {
        const int a_row = lane & 15, a_ku = lane >> 4;
        #pragma unroll
        for (int st = 0; st < 4; st++) {
            uint32_t off = SWZ((uint32_t)((wid*16 + a_row) * 128 + (st*2 + a_ku) * 16));
            ldsm4(sQ + off, qh[st]);
            ldsm4(sQ + AQ_TILE + off, ql[st]);
        }
    }

    float o_acc[8][4];
    #pragma unroll
    for (int jj = 0; jj < 8; jj++)
        #pragma unroll
        for (int c = 0; c < 4; c++) o_acc[jj][c] = 0.0f;
    float row_max[2] = {-1e30f, -1e30f}, row_l[2] = {0.0f, 0.0f};

    const int b_row = ((lane >> 4) << 3) + (lane & 7);
    const int b_ku  = (lane >> 3) & 1;
    const int v_row = lane & 15;
    const int v_cb  = ((lane >> 4) << 3) * 2;   // byte offset of d within row
    const float scale = 0.125f;

    #pragma unroll 1
    for (int kb = 0; kb < nkt; kb++) {
        if (kb == nkt - 1) cp_wait<0>(); else cp_wait<1>();
        __syncthreads();
        const uint32_t sb = sKV + (kb & 1) * AKV_STAGE;
        const uint32_t sKh = sb, sKl = sb + AKV_TILE;
        const uint32_t sVh = sb + 2*AKV_TILE, sVl = sb + 3*AKV_TILE;

        // ---- S = Q K^T ----
        float sacc[8][4];
        #pragma unroll
        for (int jj = 0; jj < 8; jj++)
            #pragma unroll
            for (int c = 0; c < 4; c++) sacc[jj][c] = 0.0f;

        #pragma unroll
        for (int st = 0; st < 4; st++) {
            const int cu = st * 2;
            uint32_t kh[4][4], kl[4][4];
            #pragma unroll
            for (int jn = 0; jn < 4; jn++) {
                uint32_t off = SWZ((uint32_t)((jn*16 + b_row) * 128 + (cu + b_ku) * 16));
                ldsm4(sKh + off, kh[jn]);
                ldsm4(sKl + off, kl[jn]);
            }
            #pragma unroll
            for (int jj = 0; jj < 8; jj++) {
                const int j16 = jj >> 1, h = (jj & 1) * 2;
                mma16816(sacc[jj], qh[st], kh[j16][h], kh[j16][h+1]);
                mma16816(sacc[jj], qh[st], kl[j16][h], kl[j16][h+1]);
                mma16816(sacc[jj], ql[st], kh[j16][h], kh[j16][h+1]);
            }
        }

        // ---- online softmax (P left in sacc, fp32) ----
        const bool tmask = (kb >= 2 * qt);
        #pragma unroll
        for (int rh = 0; rh < 2; rh++) {
            const int grow = s0 + wid*16 + (lane >> 2) + rh*8;
            float mx = -1e30f;
            #pragma unroll
            for (int jj = 0; jj < 8; jj++)
                #pragma unroll
                for (int dc = 0; dc < 2; dc++) {
                    float v = sacc[jj][rh*2+dc] * scale;
                    if (tmask && (kb*64 + jj*8 + 2*(lane&3) + dc > grow)) v = -1e30f;
                    sacc[jj][rh*2+dc] = v;
                    mx = fmaxf(mx, v);
                }
            mx = fmaxf(mx, __shfl_xor_sync(0xffffffffu, mx, 1));
            mx = fmaxf(mx, __shfl_xor_sync(0xffffffffu, mx, 2));
            float mnew = fmaxf(row_max[rh], mx);
            float corr = __expf(row_max[rh] - mnew);
            row_max[rh] = mnew;
            float sum = 0.0f;
            #pragma unroll
            for (int jj = 0; jj < 8; jj++)
                #pragma unroll
                for (int dc = 0; dc < 2; dc++) {
                    float pv = __expf(sacc[jj][rh*2+dc] - mnew);
                    sacc[jj][rh*2+dc] = pv;
                    sum += pv;
                }
            sum += __shfl_xor_sync(0xffffffffu, sum, 1);
            sum += __shfl_xor_sync(0xffffffffu, sum, 2);
            row_l[rh] = row_l[rh] * corr + sum;
            #pragma unroll
            for (int jj = 0; jj < 8; jj++) {
                o_acc[jj][rh*2]   *= corr;
                o_acc[jj][rh*2+1] *= corr;
            }
        }

        // ---- O += P V ----
        #pragma unroll
        for (int kk = 0; kk < 4; kk++) {
            uint32_t ph[4], pl[4];
            #pragma unroll
            for (int u = 0; u < 4; u++) {
                const int jj = 2*kk + (u >> 1), cb = (u & 1) * 2;
                float x = sacc[jj][cb], y = sacc[jj][cb+1];
                float hx = __bfloat162float(__float2bfloat16_rn(x));
                float hy = __bfloat162float(__float2bfloat16_rn(y));
                ph[u] = pack_bf16(hx, hy);
                pl[u] = pack_bf16(x - hx, y - hy);
            }
            uint32_t vh[4][4], vl[4][4];
            #pragma unroll
            for (int jv = 0; jv < 4; jv++) {
                uint32_t off = SWZ((uint32_t)((kk*16 + v_row) * 128 + jv*32 + v_cb));
                ldsm4t(sVh + off, vh[jv]);
                ldsm4t(sVl + off, vl[jv]);
            }
            #pragma unroll
            for (int jj = 0; jj < 8; jj++) {
                const int j16 = jj >> 1, h = (jj & 1) * 2;
                mma16816(o_acc[jj], ph, vh[j16][h], vh[j16][h+1]);
                mma16816(o_acc[jj], ph, vl[j16][h], vl[j16][h+1]);
                mma16816(o_acc[jj], pl, vh[j16][h], vh[j16][h+1]);
            }
        }
        __syncthreads();
        if (kb + 2 < nkt) fill_kv(kb & 1, kb + 2);
    }

    // ---- epilogue: normalize, split, store bf16 hi/lo [b][s][D] ----
    const int b = bh >> 4, h = bh & 15;
    const float inv0 = 1.0f / row_l[0], inv1 = 1.0f / row_l[1];
    #pragma unroll
    for (int jj = 0; jj < 8; jj++) {
        #pragma unroll
        for (int rh = 0; rh < 2; rh++) {
            const int row = s0 + wid*16 + (lane >> 2) + rh*8;
            const int d   = jj*8 + 2*(lane & 3);
            const float inv = rh ? inv1 : inv0;
            float x = o_acc[jj][rh*2] * inv, y = o_acc[jj][rh*2+1] * inv;
            float hx = __bfloat162float(__float2bfloat16_rn(x));
            float hy = __bfloat162float(__float2bfloat16_rn(y));
            size_t di = ((size_t)(b * SS + row)) * DM + h * HD + d;
            *(uint32_t*)(g_xhi + di) = pack_bf16(hx, hy);
            *(uint32_t*)(g_xlo + di) = pack_bf16(x - hx, y - hy);
        }
    }
}

// ---------------------------------------------------------------------------
extern "C" void kernel_launch(void* const* d_in, const int* in_sizes, int n_in,
                              void* d_out, int out_size)
{
    const float* x  = (const float*)d_in[0];
    const int*  pos = (const int*)  d_in[1];
    const float* w[4] = { (const float*)d_in[2], (const float*)d_in[3],
                          (const float*)d_in[4], (const float*)d_in[5] };
    float* out = (float*)d_out;

    void* p;
    cudaGetSymbolAddress(&p, g_lin);   float* lin = (float*)p;
    cudaGetSymbolAddress(&p, g_xhi);   __nv_bfloat16* xhi = (__nv_bfloat16*)p;
    cudaGetSymbolAddress(&p, g_xlo);   __nv_bfloat16* xlo = (__nv_bfloat16*)p;
    cudaGetSymbolAddress(&p, g_whi);   __nv_bfloat16* whi = (__nv_bfloat16*)p;
    cudaGetSymbolAddress(&p, g_wlo);   __nv_bfloat16* wlo = (__nv_bfloat16*)p;

    cudaFuncSetAttribute(gemm_hmma, cudaFuncAttributeMaxDynamicSharedMemorySize, GK_SMEM);
    cudaFuncSetAttribute(attn_hmma, cudaFuncAttributeMaxDynamicSharedMemorySize, ASMEM);

    // 0) split-convert x and weights to bf16 hi/lo
    conv_hilo<<<(BSD/4 + 255)/256, 256>>>((const float4*)x, xhi, xlo, BSD/4);
    for (int z = 0; z < 4; z++)
        conv_hilo<<<(DM*DM/4 + 255)/256, 256>>>((const float4*)w[z],
                                                whi + (size_t)z*DM*DM,
                                                wlo + (size_t)z*DM*DM, DM*DM/4);

    // 1) q,k,v = x @ {wq,wk,wv}^T
    gemm_hmma<<<dim3(DM/128, MT/128, 3), 512, GK_SMEM>>>(xhi, xlo, whi, wlo, lin);

    // 2) RoPE + head split + hi/lo
    const int total = 3 * BB * SS * NH * (HD/2);
    rope_split_bf16<<<(total + 255) / 256, 256>>>(pos);

    // 3) HMMA flash attention -> xhi/xlo (bf16 hi/lo, [b,s,D])
    attn_hmma<<<dim3(SS/128, BB*NH), 256, ASMEM>>>();

    // 4) out = attn @ wo^T
    gemm_hmma<<<dim3(DM/128, MT/128, 1), 512, GK_SMEM>>>(xhi, xlo,
                                                         whi + 3*(size_t)DM*DM,
                                                         wlo + 3*(size_t)DM*DM, out);
}

// round 9
// speedup vs baseline: 3.3630x; 1.0943x over previous
#include <cuda_runtime.h>
#include <cuda_bf16.h>
#include <math.h>
#include <stdint.h>

#define BB 4
#define SS 2048
#define DM 1024
#define NH 16
#define HD 64
#define MT (BB*SS)          // 8192 rows
#define BSD (MT*DM)         // 8,388,608 elements per matrix

// Scratch (static device globals)
static __device__ __align__(16) __nv_bfloat16 g_xhi[BSD];   // x hi / attn-out hi
static __device__ __align__(16) __nv_bfloat16 g_xlo[BSD];
static __device__ __align__(16) __nv_bfloat16 g_whi[4*DM*DM];
static __device__ __align__(16) __nv_bfloat16 g_wlo[4*DM*DM];
static __device__ __align__(16) __nv_bfloat16 g_qhi[BSD], g_qlo[BSD];
static __device__ __align__(16) __nv_bfloat16 g_khi[BSD], g_klo[BSD];
static __device__ __align__(16) __nv_bfloat16 g_vhi[BSD], g_vlo[BSD];

// ---------------------------------------------------------------------------
// PTX helpers (compute_103 baseline: mma.sync / ldmatrix / cp.async)
// ---------------------------------------------------------------------------
__device__ __forceinline__ uint32_t smem_u32(const void* p) {
    uint32_t a;
    asm("{ .reg .u64 t; cvta.to.shared.u64 t, %1; cvt.u32.u64 %0, t; }" : "=r"(a) : "l"(p));
    return a;
}
__device__ __forceinline__ void cp16(uint32_t saddr, const void* g) {
    asm volatile("cp.async.cg.shared.global [%0], [%1], 16;" :: "r"(saddr), "l"(g) : "memory");
}
__device__ __forceinline__ void cp_commit() {
    asm volatile("cp.async.commit_group;" ::: "memory");
}
template <int N>
__device__ __forceinline__ void cp_wait() {
    asm volatile("cp.async.wait_group %0;" :: "n"(N) : "memory");
}
__device__ __forceinline__ void ldsm4(uint32_t addr, uint32_t r[4]) {
    asm volatile("ldmatrix.sync.aligned.m8n8.x4.shared.b16 {%0,%1,%2,%3}, [%4];"
                 : "=r"(r[0]), "=r"(r[1]), "=r"(r[2]), "=r"(r[3]) : "r"(addr));
}
__device__ __forceinline__ void ldsm4t(uint32_t addr, uint32_t r[4]) {
    asm volatile("ldmatrix.sync.aligned.m8n8.x4.trans.shared.b16 {%0,%1,%2,%3}, [%4];"
                 : "=r"(r[0]), "=r"(r[1]), "=r"(r[2]), "=r"(r[3]) : "r"(addr));
}
__device__ __forceinline__ void mma16816(float c[4], const uint32_t a[4],
                                         uint32_t b0, uint32_t b1) {
    asm volatile(
        "mma.sync.aligned.m16n8k16.row.col.f32.bf16.bf16.f32 "
        "{%0,%1,%2,%3}, {%4,%5,%6,%7}, {%8,%9}, {%0,%1,%2,%3};"
        : "+f"(c[0]), "+f"(c[1]), "+f"(c[2]), "+f"(c[3])
        : "r"(a[0]), "r"(a[1]), "r"(a[2]), "r"(a[3]), "r"(b0), "r"(b1));
}
#define SWZ(off) ((off) ^ (((off) >> 3) & 0x70))

__device__ __forceinline__ uint32_t pack_bf16(float x, float y) {
    __nv_bfloat162 t(__float2bfloat16_rn(x), __float2bfloat16_rn(y));
    return *(uint32_t*)&t;
}

// ---------------------------------------------------------------------------
// fp32 -> bf16 (hi, lo) split conversion for x.  n4 = elems/4.
// ---------------------------------------------------------------------------
__global__ void conv_hilo(const float4* __restrict__ src,
                          __nv_bfloat16* __restrict__ hi,
                          __nv_bfloat16* __restrict__ lo, int n4)
{
    int i = blockIdx.x * blockDim.x + threadIdx.x;
    if (i >= n4) return;
    float4 v = src[i];
    float f[4] = {v.x, v.y, v.z, v.w};
    __nv_bfloat162 h2[2], l2[2];
    #pragma unroll
    for (int j = 0; j < 2; j++) {
        __nv_bfloat16 h0 = __float2bfloat16_rn(f[2*j]);
        __nv_bfloat16 h1 = __float2bfloat16_rn(f[2*j+1]);
        __nv_bfloat16 l0 = __float2bfloat16_rn(f[2*j]   - __bfloat162float(h0));
        __nv_bfloat16 l1 = __float2bfloat16_rn(f[2*j+1] - __bfloat162float(h1));
        h2[j] = __nv_bfloat162(h0, h1);
        l2[j] = __nv_bfloat162(l0, l1);
    }
    *(uint2*)(hi + 4*(size_t)i) = *(uint2*)h2;
    *(uint2*)(lo + 4*(size_t)i) = *(uint2*)l2;
}

// All 4 weight matrices in one launch (blockIdx.y selects the matrix).
__global__ void conv_w(const float4* __restrict__ w0, const float4* __restrict__ w1,
                       const float4* __restrict__ w2, const float4* __restrict__ w3)
{
    const int z = blockIdx.y;
    const float4* src = (z == 0) ? w0 : (z == 1) ? w1 : (z == 2) ? w2 : w3;
    int i = blockIdx.x * blockDim.x + threadIdx.x;          // < DM*DM/4
    float4 v = src[i];
    float f[4] = {v.x, v.y, v.z, v.w};
    __nv_bfloat162 h2[2], l2[2];
    #pragma unroll
    for (int j = 0; j < 2; j++) {
        __nv_bfloat16 h0 = __float2bfloat16_rn(f[2*j]);
        __nv_bfloat16 h1 = __float2bfloat16_rn(f[2*j+1]);
        __nv_bfloat16 l0 = __float2bfloat16_rn(f[2*j]   - __bfloat162float(h0));
        __nv_bfloat16 l1 = __float2bfloat16_rn(f[2*j+1] - __bfloat162float(h1));
        h2[j] = __nv_bfloat162(h0, h1);
        l2[j] = __nv_bfloat162(l0, l1);
    }
    size_t o = (size_t)z * DM * DM + 4*(size_t)i;
    *(uint2*)(g_whi + o) = *(uint2*)h2;
    *(uint2*)(g_wlo + o) = *(uint2*)l2;
}

// ---------------------------------------------------------------------------
// HMMA split-bf16 GEMM v2: C[m][n] = sum_k A[m][k] * W[n][k]
// 128x128 CTA tile, 256 threads (8 warps), warp tile 64x32 (4 m-atoms x 4 n-atoms).
// K-chunk 64, 3-stage cp.async pipeline (192KB smem), one sync per chunk.
// ROPE=true: fused RoPE + head-split + bf16 hi/lo epilogue -> g_{q,k,v}{hi,lo}.
// ROPE=false: plain fp32 epilogue -> C.
// ---------------------------------------------------------------------------
#define GK_TILE   16384                 // 128 rows x 128B (64 bf16)
#define GK_STAGE  (4*GK_TILE)           // Ahi, Alo, Bhi, Blo = 64KB
#define GK_NST    3
#define GK_SMEM   (GK_NST*GK_STAGE)     // 192KB
#define NKCH      16                    // 1024 / 64

template<bool ROPE>
__global__ void __launch_bounds__(256, 1) gemm_hmma(
    const __nv_bfloat16* __restrict__ Ahi, const __nv_bfloat16* __restrict__ Alo,
    const __nv_bfloat16* __restrict__ Whi, const __nv_bfloat16* __restrict__ Wlo,
    const int* __restrict__ pos, float* __restrict__ C)
{
    extern __shared__ char smem[];
    const uint32_t sbase = smem_u32(smem);
    const int tid = threadIdx.x, lane = tid & 31, wid = tid >> 5;
    const int n0 = blockIdx.x * 128, m0 = blockIdx.y * 128, z = blockIdx.z;

    const __nv_bfloat16* __restrict__ srcs[4] = {
        Ahi + (size_t)m0 * DM,
        Alo + (size_t)m0 * DM,
        Whi + (size_t)z * DM * DM + (size_t)n0 * DM,
        Wlo + (size_t)z * DM * DM + (size_t)n0 * DM };

    auto fill = [&](int st, int kt) {
        uint32_t sb = sbase + st * GK_STAGE;
        #pragma unroll
        for (int t = 0; t < 4; t++) {
            const __nv_bfloat16* s = srcs[t] + kt * 64;
            #pragma unroll
            for (int j = 0; j < 4; j++) {
                int idx = j * 256 + tid;
                int row = idx >> 3, cu = idx & 7;
                cp16(sb + t * GK_TILE + SWZ((uint32_t)(row * 128 + cu * 16)),
                     s + (size_t)row * DM + cu * 8);
            }
        }
        cp_commit();
    };

    // warp tiling: 2 warp-rows (64 m each), 4 warp-cols (32 n each)
    const int wm = (wid & 1) * 64;
    const int wn = (wid >> 1) * 32;
    const int a_row = lane & 15;
    const int a_ku  = lane >> 4;
    const int b_row = ((lane >> 4) << 3) + (lane & 7);
    const int b_ku  = (lane >> 3) & 1;

    float acc[4][4][4];
    #pragma unroll
    for (int i = 0; i < 4; i++)
        #pragma unroll
        for (int j = 0; j < 4; j++)
            #pragma unroll
            for (int c = 0; c < 4; c++) acc[i][j][c] = 0.0f;

    fill(0, 0);
    fill(1, 1);

    int st = 0;
    #pragma unroll 1
    for (int kt = 0; kt < NKCH; kt++) {
        if (kt == NKCH - 1) cp_wait<0>(); else cp_wait<1>();
        __syncthreads();

        // prefetch chunk kt+2 into the buffer freed by chunk kt-1
        if (kt + 2 < NKCH) {
            int fs = st + 2; if (fs >= GK_NST) fs -= GK_NST;
            fill(fs, kt + 2);
        }

        const uint32_t sb  = sbase + st * GK_STAGE;
        const uint32_t sAh = sb, sAl = sb + GK_TILE;
        const uint32_t sBh = sb + 2*GK_TILE, sBl = sb + 3*GK_TILE;

        #pragma unroll
        for (int q = 0; q < 4; q++) {
            const int cu = q * 2;
            uint32_t ah[4][4], al[4][4], bh[2][4], bl[2][4];
            #pragma unroll
            for (int i = 0; i < 4; i++) {
                uint32_t off = SWZ((uint32_t)((wm + i*16 + a_row) * 128 + (cu + a_ku) * 16));
                ldsm4(sAh + off, ah[i]);
                ldsm4(sAl + off, al[i]);
            }
            #pragma unroll
            for (int j = 0; j < 2; j++) {
                uint32_t off = SWZ((uint32_t)((wn + j*16 + b_row) * 128 + (cu + b_ku) * 16));
                ldsm4(sBh + off, bh[j]);
                ldsm4(sBl + off, bl[j]);
            }
            #pragma unroll
            for (int i = 0; i < 4; i++)
                #pragma unroll
                for (int jj = 0; jj < 4; jj++) {
                    const int j16 = jj >> 1, h = (jj & 1) * 2;
                    mma16816(acc[i][jj], ah[i], bh[j16][h], bh[j16][h+1]);
                    mma16816(acc[i][jj], ah[i], bl[j16][h], bl[j16][h+1]);
                    mma16816(acc[i][jj], al[i], bh[j16][h], bh[j16][h+1]);
                }
        }
        if (++st == GK_NST) st = 0;
    }

    const int er = lane >> 2;
    const int ec = (lane & 3) * 2;

    if constexpr (!ROPE) {
        // plain fp32 epilogue
        #pragma unroll
        for (int i = 0; i < 4; i++)
            #pragma unroll
            for (int jj = 0; jj < 4; jj++) {
                const int row = m0 + wm + i*16 + er;
                const int col = n0 + wn + jj*8 + ec;
                *(float2*)(C + (size_t)row * DM + col)       = make_float2(acc[i][jj][0], acc[i][jj][1]);
                *(float2*)(C + (size_t)(row + 8) * DM + col) = make_float2(acc[i][jj][2], acc[i][jj][3]);
            }
    } else {
        // fused RoPE (z<2) + head split + bf16 hi/lo epilogue
        __nv_bfloat16* hiA = (z == 0) ? g_qhi : (z == 1 ? g_khi : g_vhi);
        __nv_bfloat16* loA = (z == 0) ? g_qlo : (z == 1 ? g_klo : g_vlo);
        float ifr[4];
        if (z < 2) {
            #pragma unroll
            for (int jj = 0; jj < 4; jj++) {
                int dcol = (wn & 32) + jj*8 + ec;        // even d index within head
                ifr[jj] = __expf(-(float)dcol * (9.210340371976184f / 64.0f));
            }
        }
        #pragma unroll
        for (int i = 0; i < 4; i++) {
            #pragma unroll
            for (int half = 0; half < 2; half++) {
                const int row = m0 + wm + i*16 + er + half*8;   // global m = b*SS+s
                const int b = row >> 11, s = row & (SS - 1);
                int ps = 0;
                if (z < 2) ps = pos[row];
                #pragma unroll
                for (int jj = 0; jj < 4; jj++) {
                    const int col = n0 + wn + jj*8 + ec;
                    float e = acc[i][jj][half*2], o = acc[i][jj][half*2+1];
                    if (z < 2) {
                        float sn, cs;
                        sincosf((float)ps * ifr[jj], &sn, &cs);
                        float e2 = e * cs - o * sn;
                        o        = e * sn + o * cs;
                        e = e2;
                    }
                    float eh = __bfloat162float(__float2bfloat16_rn(e));
                    float oh = __bfloat162float(__float2bfloat16_rn(o));
                    const int h = col >> 6, d = col & 63;
                    size_t di = ((size_t)((b << 4) + h) * SS + s) * HD + d;
                    *(uint32_t*)(hiA + di) = pack_bf16(eh, oh);
                    *(uint32_t*)(loA + di) = pack_bf16(e - eh, o - oh);
                }
            }
        }
    }
}

// ---------------------------------------------------------------------------
// HMMA flash attention (verified round-6 version, unchanged)
// ---------------------------------------------------------------------------
#define AQ_TILE 16384
#define AKV_TILE 8192
#define AKV_STAGE (4*AKV_TILE)
#define ASMEM (2*AQ_TILE + 2*AKV_STAGE)   // 96KB

__global__ void __launch_bounds__(256, 1) attn_hmma()
{
    extern __shared__ char smem[];
    const uint32_t sbase = smem_u32(smem);
    const int tid = threadIdx.x, lane = tid & 31, wid = tid >> 5;
    const int qt = (int)gridDim.x - 1 - (int)blockIdx.x;
    const int bh = blockIdx.y;
    const int s0 = qt * 128;
    const int nkt = 2 * qt + 2;

    const size_t bhoff = (size_t)bh * SS * HD;
    const __nv_bfloat16* Qh = g_qhi + bhoff + (size_t)s0 * HD;
    const __nv_bfloat16* Ql = g_qlo + bhoff + (size_t)s0 * HD;
    const __nv_bfloat16* kvsrc[4] = { g_khi + bhoff, g_klo + bhoff,
                                      g_vhi + bhoff, g_vlo + bhoff };

    const uint32_t sQ  = sbase;
    const uint32_t sKV = sbase + 2*AQ_TILE;

    {
        #pragma unroll
        for (int j = 0; j < 4; j++) {
            int idx = j * 256 + tid;
            int row = idx >> 3, cu = idx & 7;
            uint32_t off = SWZ((uint32_t)(row * 128 + cu * 16));
            cp16(sQ + off,           Qh + (size_t)row * HD + cu * 8);
            cp16(sQ + AQ_TILE + off, Ql + (size_t)row * HD + cu * 8);
        }
        cp_commit();
    }
    auto fill_kv = [&](int st, int kb) {
        uint32_t sb = sKV + st * AKV_STAGE;
        #pragma unroll
        for (int t = 0; t < 4; t++) {
            const __nv_bfloat16* s = kvsrc[t] + (size_t)kb * 64 * HD;
            #pragma unroll
            for (int r = 0; r < 2; r++) {
                int idx = r * 256 + tid;
                int row = idx >> 3, cu = idx & 7;
                cp16(sb + t * AKV_TILE + SWZ((uint32_t)(row * 128 + cu * 16)),
                     s + (size_t)row * HD + cu * 8);
            }
        }
        cp_commit();
    };
    fill_kv(0, 0);
    fill_kv(1, 1);

    cp_wait<2>();
    __syncthreads();
    uint32_t qh[4][4], ql[4][4];
    {
        const int a_row = lane & 15, a_ku = lane >> 4;
        #pragma unroll
        for (int st = 0; st < 4; st++) {
            uint32_t off = SWZ((uint32_t)((wid*16 + a_row) * 128 + (st*2 + a_ku) * 16));
            ldsm4(sQ + off, qh[st]);
            ldsm4(sQ + AQ_TILE + off, ql[st]);
        }
    }

    float o_acc[8][4];
    #pragma unroll
    for (int jj = 0; jj < 8; jj++)
        #pragma unroll
        for (int c = 0; c < 4; c++) o_acc[jj][c] = 0.0f;
    float row_max[2] = {-1e30f, -1e30f}, row_l[2] = {0.0f, 0.0f};

    const int b_row = ((lane >> 4) << 3) + (lane & 7);
    const int b_ku  = (lane >> 3) & 1;
    const int v_row = lane & 15;
    const int v_cb  = ((lane >> 4) << 3) * 2;
    const float scale = 0.125f;

    #pragma unroll 1
    for (int kb = 0; kb < nkt; kb++) {
        if (kb == nkt - 1) cp_wait<0>(); else cp_wait<1>();
        __syncthreads();
        const uint32_t sb = sKV + (kb & 1) * AKV_STAGE;
        const uint32_t sKh = sb, sKl = sb + AKV_TILE;
        const uint32_t sVh = sb + 2*AKV_TILE, sVl = sb + 3*AKV_TILE;

        float sacc[8][4];
        #pragma unroll
        for (int jj = 0; jj < 8; jj++)
            #pragma unroll
            for (int c = 0; c < 4; c++) sacc[jj][c] = 0.0f;

        #pragma unroll
        for (int st = 0; st < 4; st++) {
            const int cu = st * 2;
            uint32_t kh[4][4], kl[4][4];
            #pragma unroll
            for (int jn = 0; jn < 4; jn++) {
                uint32_t off = SWZ((uint32_t)((jn*16 + b_row) * 128 + (cu + b_ku) * 16));
                ldsm4(sKh + off, kh[jn]);
                ldsm4(sKl + off, kl[jn]);
            }
            #pragma unroll
            for (int jj = 0; jj < 8; jj++) {
                const int j16 = jj >> 1, h = (jj & 1) * 2;
                mma16816(sacc[jj], qh[st], kh[j16][h], kh[j16][h+1]);
                mma16816(sacc[jj], qh[st], kl[j16][h], kl[j16][h+1]);
                mma16816(sacc[jj], ql[st], kh[j16][h], kh[j16][h+1]);
            }
        }

        const bool tmask = (kb >= 2 * qt);
        #pragma unroll
        for (int rh = 0; rh < 2; rh++) {
            const int grow = s0 + wid*16 + (lane >> 2) + rh*8;
            float mx = -1e30f;
            #pragma unroll
            for (int jj = 0; jj < 8; jj++)
                #pragma unroll
                for (int dc = 0; dc < 2; dc++) {
                    float v = sacc[jj][rh*2+dc] * scale;
                    if (tmask && (kb*64 + jj*8 + 2*(lane&3) + dc > grow)) v = -1e30f;
                    sacc[jj][rh*2+dc] = v;
                    mx = fmaxf(mx, v);
                }
            mx = fmaxf(mx, __shfl_xor_sync(0xffffffffu, mx, 1));
            mx = fmaxf(mx, __shfl_xor_sync(0xffffffffu, mx, 2));
            float mnew = fmaxf(row_max[rh], mx);
            float corr = __expf(row_max[rh] - mnew);
            row_max[rh] = mnew;
            float sum = 0.0f;
            #pragma unroll
            for (int jj = 0; jj < 8; jj++)
                #pragma unroll
                for (int dc = 0; dc < 2; dc++) {
                    float pv = __expf(sacc[jj][rh*2+dc] - mnew);
                    sacc[jj][rh*2+dc] = pv;
                    sum += pv;
                }
            sum += __shfl_xor_sync(0xffffffffu, sum, 1);
            sum += __shfl_xor_sync(0xffffffffu, sum, 2);
            row_l[rh] = row_l[rh] * corr + sum;
            #pragma unroll
            for (int jj = 0; jj < 8; jj++) {
                o_acc[jj][rh*2]   *= corr;
                o_acc[jj][rh*2+1] *= corr;
            }
        }

        #pragma unroll
        for (int kk = 0; kk < 4; kk++) {
            uint32_t ph[4], pl[4];
            #pragma unroll
            for (int u = 0; u < 4; u++) {
                const int jj = 2*kk + (u >> 1), cb = (u & 1) * 2;
                float x = sacc[jj][cb], y = sacc[jj][cb+1];
                float hx = __bfloat162float(__float2bfloat16_rn(x));
                float hy = __bfloat162float(__float2bfloat16_rn(y));
                ph[u] = pack_bf16(hx, hy);
                pl[u] = pack_bf16(x - hx, y - hy);
            }
            uint32_t vh[4][4], vl[4][4];
            #pragma unroll
            for (int jv = 0; jv < 4; jv++) {
                uint32_t off = SWZ((uint32_t)((kk*16 + v_row) * 128 + jv*32 + v_cb));
                ldsm4t(sVh + off, vh[jv]);
                ldsm4t(sVl + off, vl[jv]);
            }
            #pragma unroll
            for (int jj = 0; jj < 8; jj++) {
                const int j16 = jj >> 1, h = (jj & 1) * 2;
                mma16816(o_acc[jj], ph, vh[j16][h], vh[j16][h+1]);
                mma16816(o_acc[jj], ph, vl[j16][h], vl[j16][h+1]);
                mma16816(o_acc[jj], pl, vh[j16][h], vh[j16][h+1]);
            }
        }
        __syncthreads();
        if (kb + 2 < nkt) fill_kv(kb & 1, kb + 2);
    }

    const int b = bh >> 4, h = bh & 15;
    const float inv0 = 1.0f / row_l[0], inv1 = 1.0f / row_l[1];
    #pragma unroll
    for (int jj = 0; jj < 8; jj++) {
        #pragma unroll
        for (int rh = 0; rh < 2; rh++) {
            const int row = s0 + wid*16 + (lane >> 2) + rh*8;
            const int d   = jj*8 + 2*(lane & 3);
            const float inv = rh ? inv1 : inv0;
            float x = o_acc[jj][rh*2] * inv, y = o_acc[jj][rh*2+1] * inv;
            float hx = __bfloat162float(__float2bfloat16_rn(x));
            float hy = __bfloat162float(__float2bfloat16_rn(y));
            size_t di = ((size_t)(b * SS + row)) * DM + h * HD + d;
            *(uint32_t*)(g_xhi + di) = pack_bf16(hx, hy);
            *(uint32_t*)(g_xlo + di) = pack_bf16(x - hx, y - hy);
        }
    }
}

// ---------------------------------------------------------------------------
extern "C" void kernel_launch(void* const* d_in, const int* in_sizes, int n_in,
                              void* d_out, int out_size)
{
    const float* x  = (const float*)d_in[0];
    const int*  pos = (const int*)  d_in[1];
    const float* wq = (const float*)d_in[2];
    const float* wk = (const float*)d_in[3];
    const float* wv = (const float*)d_in[4];
    const float* wo = (const float*)d_in[5];
    float* out = (float*)d_out;

    void* p;
    cudaGetSymbolAddress(&p, g_xhi);   __nv_bfloat16* xhi = (__nv_bfloat16*)p;
    cudaGetSymbolAddress(&p, g_xlo);   __nv_bfloat16* xlo = (__nv_bfloat16*)p;
    cudaGetSymbolAddress(&p, g_whi);   __nv_bfloat16* whi = (__nv_bfloat16*)p;
    cudaGetSymbolAddress(&p, g_wlo);   __nv_bfloat16* wlo = (__nv_bfloat16*)p;

    cudaFuncSetAttribute(gemm_hmma<true>,  cudaFuncAttributeMaxDynamicSharedMemorySize, GK_SMEM);
    cudaFuncSetAttribute(gemm_hmma<false>, cudaFuncAttributeMaxDynamicSharedMemorySize, GK_SMEM);
    cudaFuncSetAttribute(attn_hmma, cudaFuncAttributeMaxDynamicSharedMemorySize, ASMEM);

    // 0) split-convert x and weights to bf16 hi/lo
    conv_hilo<<<(BSD/4 + 255)/256, 256>>>((const float4*)x, xhi, xlo, BSD/4);
    conv_w<<<dim3(DM*DM/4/256, 4), 256>>>((const float4*)wq, (const float4*)wk,
                                          (const float4*)wv, (const float4*)wo);

    // 1) q,k,v = x @ {wq,wk,wv}^T with fused RoPE + head split -> g_{q,k,v}{hi,lo}
    gemm_hmma<true><<<dim3(DM/128, MT/128, 3), 256, GK_SMEM>>>(xhi, xlo, whi, wlo, pos, nullptr);

    // 2) HMMA flash attention -> g_xhi/g_xlo (bf16 hi/lo, [b,s,D])
    attn_hmma<<<dim3(SS/128, BB*NH), 256, ASMEM>>>();

    // 3) out = attn @ wo^T
    gemm_hmma<false><<<dim3(DM/128, MT/128, 1), 256, GK_SMEM>>>(
        xhi, xlo, whi + 3*(size_t)DM*DM, wlo + 3*(size_t)DM*DM, nullptr, out);
}